// round 9
// baseline (speedup 1.0000x reference)
#include <cuda_runtime.h>
#include <cstdint>

#define BB 64
#define TT 512
#define EE 768
#define HH 256
#define VV 3072

__device__ float g_x[TT * BB * HH];   // xWxh laid out [t][b][h]
__device__ float g_h[BB * HH];        // final hidden

// ---------- f32x2 helpers ----------
__device__ __forceinline__ unsigned long long pack2(float lo, float hi) {
    unsigned long long r;
    asm("mov.b64 %0, {%1, %2};" : "=l"(r) : "f"(lo), "f"(hi));
    return r;
}
__device__ __forceinline__ void unpack2(unsigned long long v, float& lo, float& hi) {
    asm("mov.b64 {%0, %1}, %2;" : "=f"(lo), "=f"(hi) : "l"(v));
}
__device__ __forceinline__ unsigned long long fma2(unsigned long long a,
                                                   unsigned long long b,
                                                   unsigned long long c) {
    unsigned long long d;
    asm("fma.rn.f32x2 %0, %1, %2, %3;" : "=l"(d) : "l"(a), "l"(b), "l"(c));
    return d;
}
__device__ __forceinline__ void cp16(uint32_t dst, const void* src) {
    asm volatile("cp.async.cg.shared.global [%0], [%1], 16;" :: "r"(dst), "l"(src));
}

// =====================================================================
// Phase 1: g_x[t][b][h] = sum_e emb[idx[b][t]][e] * Wxh[e][h]
// (unchanged from R7: 304us, fma-floor-limited)
// =====================================================================
__global__ __launch_bounds__(256, 2)
void gemm_emb(const int* __restrict__ idx, const float* __restrict__ emb,
              const float* __restrict__ Wxh) {
    __shared__ __align__(16) float As[2][128][16];
    __shared__ __align__(16) float Bs[2][16][128];

    const int tid = threadIdx.x;
    const int bm = blockIdx.y;
    const int bn = blockIdx.x;

    const int tx = tid & 15;
    const int ty = tid >> 4;

    const int ar   = tid >> 1;
    const int acol = (tid & 1) * 8;
    const long rr = idx[bm * 128 + ar];
    const float* asrc = emb + rr * EE + acol;

    const int br   = tid >> 4;
    const int bcol = (tid & 15) * 8;
    const float* bsrc = Wxh + (size_t)br * HH + bn * 128 + bcol;

    const uint32_t as_base = (uint32_t)__cvta_generic_to_shared(&As[0][0][0]);
    const uint32_t bs_base = (uint32_t)__cvta_generic_to_shared(&Bs[0][0][0]);
    const uint32_t aD = as_base + (ar * 16 + acol) * 4;
    const uint32_t bD = bs_base + (br * 128 + bcol) * 4;

    unsigned long long c2[8][4];
#pragma unroll
    for (int i = 0; i < 8; i++)
#pragma unroll
        for (int j = 0; j < 4; j++) c2[i][j] = 0ull;

    const int NT = EE / 16;  // 48

#define ISSUE_TILE(n, s)                                                     \
    do {                                                                     \
        const float* a_ = asrc + (n) * 16;                                   \
        const float* b_ = bsrc + (size_t)(n) * 16 * HH;                      \
        cp16(aD + (s) * 8192, a_);      cp16(aD + (s) * 8192 + 16, a_ + 4);  \
        cp16(bD + (s) * 8192, b_);      cp16(bD + (s) * 8192 + 16, b_ + 4);  \
        asm volatile("cp.async.commit_group;");                              \
    } while (0)

#define COMPUTE_STEP(i, s)                                                   \
    do {                                                                     \
        asm volatile("cp.async.wait_group 0;");                              \
        __syncthreads();                                                     \
        if ((i) + 1 < NT) ISSUE_TILE((i) + 1, (s) ^ 1);                      \
        const uint32_t bld = bs_base + (s) * 8192 + tx * 32;                 \
        const uint32_t ald = as_base + (s) * 8192 + ty * 8 * 64;             \
        _Pragma("unroll")                                                    \
        for (int kq = 0; kq < 4; kq++) {                                     \
            float4 av[8];                                                    \
            _Pragma("unroll")                                                \
            for (int ii = 0; ii < 8; ii++) {                                 \
                uint32_t aa = ald + ii * 64 + kq * 16;                       \
                asm volatile("ld.shared.v4.f32 {%0,%1,%2,%3}, [%4];"         \
                    : "=f"(av[ii].x), "=f"(av[ii].y),                        \
                      "=f"(av[ii].z), "=f"(av[ii].w) : "r"(aa));             \
            }                                                                \
            _Pragma("unroll")                                                \
            for (int m = 0; m < 4; m++) {                                    \
                const int k = kq * 4 + m;                                    \
                unsigned long long b2[4];                                    \
                uint32_t ba = bld + k * 512;                                 \
                asm volatile("ld.shared.v2.u64 {%0,%1}, [%2];"               \
                             : "=l"(b2[0]), "=l"(b2[1]) : "r"(ba));          \
                asm volatile("ld.shared.v2.u64 {%0,%1}, [%2];"               \
                             : "=l"(b2[2]), "=l"(b2[3]) : "r"(ba + 16));     \
                _Pragma("unroll")                                            \
                for (int ii = 0; ii < 8; ii++) {                             \
                    float a_ = (m == 0) ? av[ii].x : (m == 1) ? av[ii].y     \
                             : (m == 2) ? av[ii].z : av[ii].w;               \
                    unsigned long long a2 = pack2(a_, a_);                   \
                    _Pragma("unroll")                                        \
                    for (int j = 0; j < 4; j++)                              \
                        c2[ii][j] = fma2(a2, b2[j], c2[ii][j]);              \
                }                                                            \
            }                                                                \
        }                                                                    \
    } while (0)

    ISSUE_TILE(0, 0);
    for (int i = 0; i < NT; i += 2) {
        COMPUTE_STEP(i, 0);
        COMPUTE_STEP(i + 1, 1);
    }
#undef ISSUE_TILE
#undef COMPUTE_STEP

#pragma unroll
    for (int i = 0; i < 8; i++) {
        int m = bm * 128 + ty * 8 + i;
        int b = m >> 9;
        int t = m & 511;
        float* outp = g_x + (size_t)t * (BB * HH) + b * HH + bn * 128 + tx * 8;
        float4 v0, v1;
        unpack2(c2[i][0], v0.x, v0.y); unpack2(c2[i][1], v0.z, v0.w);
        unpack2(c2[i][2], v1.x, v1.y); unpack2(c2[i][3], v1.z, v1.w);
        *reinterpret_cast<float4*>(outp)     = v0;
        *reinterpret_cast<float4*>(outp + 4) = v1;
    }
}

// =====================================================================
// Phase 2: recurrent scan. Cluster of 2 CTAs per batch, 512 thr/CTA.
// Thread map: jl = tid>>2 (0..127), c = tid&3 (quad owns 4 i-chunks
// of 64). Quad partials reduced with 2x shfl_xor -- NO psum smem, NO
// __syncthreads in the loop. ONE barrier.cluster per step: it is both
// the CTA barrier and the cluster release/acquire for local stores +
// peer DSMEM stores (exact guarantee R2/R7 passed on).
// w2 indexing is 100% static (R6 lesson: dynamic index -> local spill).
// =====================================================================
__global__ __launch_bounds__(512, 1) __cluster_dims__(2, 1, 1)
void rnn_scan(const float* __restrict__ Whh, const float* __restrict__ Bh) {
    __shared__ __align__(16) float hbuf[2][256];

    const int tid = threadIdx.x;
    const int b = blockIdx.x >> 1;
    uint32_t rank;
    asm("mov.u32 %0, %%cluster_ctarank;" : "=r"(rank));
    const uint32_t prank = rank ^ 1u;

    const int jl = tid >> 2;       // 0..127
    const int c  = tid & 3;        // i-chunk (adjacent lanes)
    const int j  = (int)rank * 128 + jl;
    const int i0 = c * 64;

    // 64 weights (rows i0..i0+63, col j) as 32 f32x2 regs, STATIC indices
    unsigned long long w2[32];
#pragma unroll
    for (int p = 0; p < 32; p++) {
        int i = i0 + 2 * p;
        w2[p] = pack2(Whh[i * HH + j], Whh[(i + 1) * HH + j]);
    }
    float bh = 0.f;
    if (c == 0) bh = Bh[j];

    const uint32_t hb_base = (uint32_t)__cvta_generic_to_shared(&hbuf[0][0]);

    uint32_t peer_h[2];
#pragma unroll
    for (int bb = 0; bb < 2; bb++) {
        uint32_t lh = hb_base + bb * 1024 + j * 4;
        asm("mapa.shared::cluster.u32 %0, %1, %2;"
            : "=r"(peer_h[bb]) : "r"(lh), "r"(prank));
    }

    if (tid < 256) hbuf[0][tid] = 0.f;
    __syncthreads();
    asm volatile("barrier.cluster.arrive.aligned;" ::: "memory");
    asm volatile("barrier.cluster.wait.aligned;"   ::: "memory");

    const float* xptr = g_x + b * HH + j;
    float xv_cur = 0.f;
    if (c == 0) xv_cur = xptr[0];

    for (int t = 0; t < TT; t++) {
        const int cur = t & 1;
        const int nb  = cur ^ 1;

        float xv = 0.f;
        if (c == 0) {
            xv = xv_cur;
            if (t + 1 < TT) xv_cur = xptr[(size_t)(t + 1) * (BB * HH)];
        }

        // partial = sum_{i in chunk of 64} Whh[i][j] * h[i]
        const uint32_t ha = hb_base + cur * 1024 + i0 * 4;
        unsigned long long acc0 = 0ull, acc1 = 0ull;
#pragma unroll
        for (int p = 0; p < 8; p++) {
            unsigned long long h0, h1, h2, h3;
            asm volatile("ld.shared.v2.u64 {%0,%1}, [%2];"
                         : "=l"(h0), "=l"(h1) : "r"(ha + p * 32));
            asm volatile("ld.shared.v2.u64 {%0,%1}, [%2];"
                         : "=l"(h2), "=l"(h3) : "r"(ha + p * 32 + 16));
            acc0 = fma2(w2[4 * p + 0], h0, acc0);
            acc1 = fma2(w2[4 * p + 1], h1, acc1);
            acc0 = fma2(w2[4 * p + 2], h2, acc0);
            acc1 = fma2(w2[4 * p + 3], h3, acc1);
        }
        float l0, u0, l1, u1;
        unpack2(acc0, l0, u0); unpack2(acc1, l1, u1);
        float part = (l0 + u0) + (l1 + u1);

        // quad reduction across c (adjacent lanes)
        part += __shfl_xor_sync(0xFFFFFFFFu, part, 1);
        part += __shfl_xor_sync(0xFFFFFFFFu, part, 2);

        if (c == 0) {
            float s = part + xv + bh;
            float hn = tanhf(s);
            hbuf[nb][j] = hn;                               // local copy
            asm volatile("st.shared::cluster.f32 [%0], %1;" // peer copy
                         :: "r"(peer_h[nb]), "f"(hn) : "memory");
            if (t == TT - 1) g_h[b * HH + j] = hn;
        }

        // single barrier per step: CTA sync + cluster release/acquire
        asm volatile("barrier.cluster.arrive.aligned;" ::: "memory");
        asm volatile("barrier.cluster.wait.aligned;"   ::: "memory");
    }
    // final iteration's barrier fenced all in-flight remote stores
}

// =====================================================================
// Phase 3: out[b][v] = g_h[b] @ Wy + By.  2 batches per CTA.
// =====================================================================
__global__ __launch_bounds__(256)
void out_proj(const float* __restrict__ Wy, const float* __restrict__ By,
              float* __restrict__ out, int out_size) {
    if (blockIdx.x == 384) {
        if (out_size >= BB * VV + BB * HH) {
            for (int i = threadIdx.x; i < BB * HH; i += 256)
                out[BB * VV + i] = g_h[i];
        }
        return;
    }
    __shared__ float hs[2][HH];
    const int b0 = (blockIdx.x / 12) * 2;
    const int vt = blockIdx.x % 12;
    const int v  = vt * 256 + threadIdx.x;

    hs[0][threadIdx.x] = g_h[b0 * HH + threadIdx.x];
    hs[1][threadIdx.x] = g_h[(b0 + 1) * HH + threadIdx.x];
    __syncthreads();

    float acc0 = 0.f, acc1 = 0.f;
#pragma unroll 8
    for (int h = 0; h < HH; h++) {
        float w = Wy[(size_t)h * VV + v];
        acc0 += hs[0][h] * w;
        acc1 += hs[1][h] * w;
    }
    float by = By[v];
    out[(size_t)b0 * VV + v]       = acc0 + by;
    out[(size_t)(b0 + 1) * VV + v] = acc1 + by;
}

// =====================================================================
extern "C" void kernel_launch(void* const* d_in, const int* in_sizes, int n_in,
                              void* d_out, int out_size) {
    const int*   idx = (const int*)d_in[0];
    const float* emb = (const float*)d_in[1];
    const float* Wxh = (const float*)d_in[2];
    const float* Whh = (const float*)d_in[3];
    const float* Wy  = (const float*)d_in[4];
    const float* By  = (const float*)d_in[5];
    const float* Bh  = (const float*)d_in[6];
    float* out = (float*)d_out;

    gemm_emb<<<dim3(2, 256), 256>>>(idx, emb, Wxh);
    rnn_scan<<<128, 512>>>(Whh, Bh);
    out_proj<<<385, 256>>>(Wy, By, out, out_size);
}

// round 10
// speedup vs baseline: 1.8682x; 1.8682x over previous
#include <cuda_runtime.h>
#include <cstdint>

#define BB 64
#define TT 512
#define EE 768
#define HH 256
#define VV 3072

__device__ float g_x[TT * BB * HH];   // xWxh laid out [t][b][h]
__device__ float g_h[BB * HH];        // final hidden

// ---------- f32x2 helpers ----------
__device__ __forceinline__ unsigned long long pack2(float lo, float hi) {
    unsigned long long r;
    asm("mov.b64 %0, {%1, %2};" : "=l"(r) : "f"(lo), "f"(hi));
    return r;
}
__device__ __forceinline__ void unpack2(unsigned long long v, float& lo, float& hi) {
    asm("mov.b64 {%0, %1}, %2;" : "=f"(lo), "=f"(hi) : "l"(v));
}
__device__ __forceinline__ unsigned long long fma2(unsigned long long a,
                                                   unsigned long long b,
                                                   unsigned long long c) {
    unsigned long long d;
    asm("fma.rn.f32x2 %0, %1, %2, %3;" : "=l"(d) : "l"(a), "l"(b), "l"(c));
    return d;
}
__device__ __forceinline__ void cp16(uint32_t dst, const void* src) {
    asm volatile("cp.async.cg.shared.global [%0], [%1], 16;" :: "r"(dst), "l"(src));
}

// =====================================================================
// Phase 1: g_x[t][b][h] = sum_e emb[idx[b][t]][e] * Wxh[e][h]
// M=32768, N=256, K=768. BM=128, BN=128, BK=16; 256 threads; 8x8 f32x2.
// A stored in smem TRANSPOSED + PRE-SPLATTED: As[k][row] = (a,a) u64.
// k-loop: 4 A v2.u64 + 4 B v2.u64 + 32 FMA2 = 40 instr (no packs).
// A staged via LDG->regs->STS (double buffer); B via cp.async.
// Dynamic smem layout (u64 units conceptually, byte offsets below):
//   As stage s: off = s*16640      (16 * 130 * 8 = 16640 B, pad row 130)
//   Bs stage s: off = 33280 + s*8192
// =====================================================================
#define GEMM_SMEM_BYTES (2 * 16640 + 2 * 8192)   // 49664

__global__ __launch_bounds__(256, 2)
void gemm_emb(const int* __restrict__ idx, const float* __restrict__ emb,
              const float* __restrict__ Wxh) {
    extern __shared__ __align__(16) char smem[];

    const int tid = threadIdx.x;
    const int bm = blockIdx.y;
    const int bn = blockIdx.x;

    const int tx = tid & 15;
    const int ty = tid >> 4;

    // A gather: thread = 1 row (ar), 8 k-values starting at acol
    const int ar   = tid >> 1;
    const int acol = (tid & 1) * 8;
    const long rr = idx[bm * 128 + ar];
    const float* asrc = emb + rr * EE + acol;

    // B: thread = 1 k-row, 8 n-values
    const int br   = tid >> 4;
    const int bcol = (tid & 15) * 8;
    const float* bsrc = Wxh + (size_t)br * HH + bn * 128 + bcol;

    const uint32_t sm_base = (uint32_t)__cvta_generic_to_shared(smem);
    const uint32_t as_base = sm_base;                 // As stages
    const uint32_t bs_base = sm_base + 2 * 16640;     // Bs stages
    const uint32_t bD = bs_base + (br * 128 + bcol) * 4;

    unsigned long long c2[8][4];
#pragma unroll
    for (int i = 0; i < 8; i++)
#pragma unroll
        for (int j = 0; j < 4; j++) c2[i][j] = 0ull;

    const int NT = EE / 16;  // 48

    float4 ra0, ra1;   // next A tile (8 floats) in regs

    // STS current A regs (duplicated+transposed) into stage s
#define STS_A(s)                                                             \
    do {                                                                     \
        const uint32_t ab = as_base + (s) * 16640 + ar * 8;                  \
        asm volatile("st.shared.b64 [%0], %1;" :: "r"(ab + (acol+0)*1040), "l"(pack2(ra0.x, ra0.x))); \
        asm volatile("st.shared.b64 [%0], %1;" :: "r"(ab + (acol+1)*1040), "l"(pack2(ra0.y, ra0.y))); \
        asm volatile("st.shared.b64 [%0], %1;" :: "r"(ab + (acol+2)*1040), "l"(pack2(ra0.z, ra0.z))); \
        asm volatile("st.shared.b64 [%0], %1;" :: "r"(ab + (acol+3)*1040), "l"(pack2(ra0.w, ra0.w))); \
        asm volatile("st.shared.b64 [%0], %1;" :: "r"(ab + (acol+4)*1040), "l"(pack2(ra1.x, ra1.x))); \
        asm volatile("st.shared.b64 [%0], %1;" :: "r"(ab + (acol+5)*1040), "l"(pack2(ra1.y, ra1.y))); \
        asm volatile("st.shared.b64 [%0], %1;" :: "r"(ab + (acol+6)*1040), "l"(pack2(ra1.z, ra1.z))); \
        asm volatile("st.shared.b64 [%0], %1;" :: "r"(ab + (acol+7)*1040), "l"(pack2(ra1.w, ra1.w))); \
    } while (0)

#define LDG_A(n)                                                             \
    do {                                                                     \
        ra0 = *reinterpret_cast<const float4*>(asrc + (n) * 16);             \
        ra1 = *reinterpret_cast<const float4*>(asrc + (n) * 16 + 4);         \
    } while (0)

#define ISSUE_B(n, s)                                                        \
    do {                                                                     \
        const float* b_ = bsrc + (size_t)(n) * 16 * HH;                      \
        cp16(bD + (s) * 8192, b_);  cp16(bD + (s) * 8192 + 16, b_ + 4);      \
        asm volatile("cp.async.commit_group;");                              \
    } while (0)

#define COMPUTE(i, s)                                                        \
    do {                                                                     \
        STS_A(s);                         /* A(i) regs -> stage s */         \
        if ((i) + 1 < NT) LDG_A((i) + 1);                                    \
        asm volatile("cp.async.wait_group 0;");  /* B(i) landed */           \
        __syncthreads();                                                     \
        if ((i) + 1 < NT) ISSUE_B((i) + 1, (s) ^ 1);                         \
        const uint32_t bld = bs_base + (s) * 8192 + tx * 32;                 \
        const uint32_t ald = as_base + (s) * 16640 + ty * 64;                \
        _Pragma("unroll")                                                    \
        for (int k = 0; k < 16; k++) {                                       \
            unsigned long long av[8], b2[4];                                 \
            uint32_t aa = ald + k * 1040;                                    \
            asm volatile("ld.shared.v2.u64 {%0,%1}, [%2];"                   \
                         : "=l"(av[0]), "=l"(av[1]) : "r"(aa));              \
            asm volatile("ld.shared.v2.u64 {%0,%1}, [%2];"                   \
                         : "=l"(av[2]), "=l"(av[3]) : "r"(aa + 16));         \
            asm volatile("ld.shared.v2.u64 {%0,%1}, [%2];"                   \
                         : "=l"(av[4]), "=l"(av[5]) : "r"(aa + 32));         \
            asm volatile("ld.shared.v2.u64 {%0,%1}, [%2];"                   \
                         : "=l"(av[6]), "=l"(av[7]) : "r"(aa + 48));         \
            uint32_t ba = bld + k * 512;                                     \
            asm volatile("ld.shared.v2.u64 {%0,%1}, [%2];"                   \
                         : "=l"(b2[0]), "=l"(b2[1]) : "r"(ba));              \
            asm volatile("ld.shared.v2.u64 {%0,%1}, [%2];"                   \
                         : "=l"(b2[2]), "=l"(b2[3]) : "r"(ba + 16));         \
            _Pragma("unroll")                                                \
            for (int ii = 0; ii < 8; ii++) {                                 \
                _Pragma("unroll")                                            \
                for (int j = 0; j < 4; j++)                                  \
                    c2[ii][j] = fma2(av[ii], b2[j], c2[ii][j]);              \
            }                                                                \
        }                                                                    \
    } while (0)

    // prologue: A(0) regs; B(0) in flight
    LDG_A(0);
    ISSUE_B(0, 0);

    for (int i = 0; i < NT; i += 2) {
        COMPUTE(i, 0);
        COMPUTE(i + 1, 1);
    }
#undef STS_A
#undef LDG_A
#undef ISSUE_B
#undef COMPUTE

    // Epilogue: m = b*512 + t  ->  g_x[t*B*H + b*H + h]
#pragma unroll
    for (int i = 0; i < 8; i++) {
        int m = bm * 128 + ty * 8 + i;
        int b = m >> 9;
        int t = m & 511;
        float* outp = g_x + (size_t)t * (BB * HH) + b * HH + bn * 128 + tx * 8;
        float4 v0, v1;
        unpack2(c2[i][0], v0.x, v0.y); unpack2(c2[i][1], v0.z, v0.w);
        unpack2(c2[i][2], v1.x, v1.y); unpack2(c2[i][3], v1.z, v1.w);
        *reinterpret_cast<float4*>(outp)     = v0;
        *reinterpret_cast<float4*>(outp + 4) = v1;
    }
}

// =====================================================================
// Phase 2: recurrent scan, PULL style. Cluster of 2 CTAs per batch,
// 512 thr/CTA. hbuf[2][128] holds ONLY this CTA's 128 h values.
// Thread map: jl = tid&127, c = tid>>7 (4 chunks of 64 rows; c is
// warp-uniform). Chunk rows in the peer's range are read via
// ld.shared::cluster (mapa'd; works for local rank too -> uniform).
// Per step: loads+FMA -> psum -> __syncthreads -> c0 combine/tanh/
// LOCAL store -> barrier.cluster (release/acquire makes local stores
// visible to peer's next-step DSMEM reads). NO remote stores at all.
// w2 indexing 100% static.
// =====================================================================
__global__ __launch_bounds__(512, 1) __cluster_dims__(2, 1, 1)
void rnn_scan(const float* __restrict__ Whh, const float* __restrict__ Bh) {
    __shared__ __align__(16) float hbuf[2][128];
    __shared__ float psum[3][128];

    const int tid = threadIdx.x;
    const int b = blockIdx.x >> 1;
    uint32_t rank;
    asm("mov.u32 %0, %%cluster_ctarank;" : "=r"(rank));

    const int jl = tid & 127;
    const int c  = tid >> 7;            // 0..3, warp-uniform
    const int j  = (int)rank * 128 + jl;
    const int i0 = c * 64;              // global row base of my chunk

    // 64 weights (rows i0..i0+63, col j) as 32 f32x2 regs, STATIC indices
    unsigned long long w2[32];
#pragma unroll
    for (int p = 0; p < 32; p++) {
        int i = i0 + 2 * p;
        w2[p] = pack2(Whh[i * HH + j], Whh[(i + 1) * HH + j]);
    }
    float bh = 0.f;
    if (c == 0) bh = Bh[j];

    const uint32_t hb_base = (uint32_t)__cvta_generic_to_shared(&hbuf[0][0]);

    // cluster address of the chunk's h slice, per buffer
    const uint32_t owner = (uint32_t)(i0 >> 7);          // CTA rank owning rows
    const uint32_t loff  = (uint32_t)((i0 & 127) * 4);   // byte offset in owner's hbuf
    uint32_t ha_buf[2];
#pragma unroll
    for (int bb = 0; bb < 2; bb++) {
        uint32_t la = hb_base + bb * 512 + loff;
        asm("mapa.shared::cluster.u32 %0, %1, %2;"
            : "=r"(ha_buf[bb]) : "r"(la), "r"(owner));
    }

    if (tid < 128) hbuf[0][tid] = 0.f;
    __syncthreads();
    asm volatile("barrier.cluster.arrive.aligned;" ::: "memory");
    asm volatile("barrier.cluster.wait.aligned;"   ::: "memory");

    const float* xptr = g_x + b * HH + j;
    float xv_cur = 0.f;
    if (c == 0) xv_cur = xptr[0];

    for (int t = 0; t < TT; t++) {
        const int cur = t & 1;
        const int nb  = cur ^ 1;

        float xv = 0.f;
        if (c == 0) {
            xv = xv_cur;
            if (t + 1 < TT) xv_cur = xptr[(size_t)(t + 1) * (BB * HH)];
        }

        // partial = sum_{i in chunk of 64} Whh[i][j] * h[i]
        // h slice read via DSMEM (local-mapped for own chunks)
        const uint32_t ha = ha_buf[cur];
        unsigned long long acc0 = 0ull, acc1 = 0ull;
#pragma unroll
        for (int p = 0; p < 8; p++) {
            unsigned long long h0, h1, h2, h3;
            asm volatile("ld.shared::cluster.v2.u64 {%0,%1}, [%2];"
                         : "=l"(h0), "=l"(h1) : "r"(ha + p * 32));
            asm volatile("ld.shared::cluster.v2.u64 {%0,%1}, [%2];"
                         : "=l"(h2), "=l"(h3) : "r"(ha + p * 32 + 16));
            acc0 = fma2(w2[4 * p + 0], h0, acc0);
            acc1 = fma2(w2[4 * p + 1], h1, acc1);
            acc0 = fma2(w2[4 * p + 2], h2, acc0);
            acc1 = fma2(w2[4 * p + 3], h3, acc1);
        }
        float l0, u0, l1, u1;
        unpack2(acc0, l0, u0); unpack2(acc1, l1, u1);
        float part = (l0 + u0) + (l1 + u1);

        if (c > 0) psum[c - 1][jl] = part;
        __syncthreads();

        if (c == 0) {
            float s = part + psum[0][jl] + psum[1][jl] + psum[2][jl] + xv + bh;
            float hn = tanhf(s);
            hbuf[nb][jl] = hn;     // LOCAL store only
            if (t == TT - 1) g_h[b * HH + j] = hn;
        }

        // one barrier per step: CTA sync + cluster release/acquire
        // (peer's next-step DSMEM reads of hbuf[nb] are ordered after this)
        asm volatile("barrier.cluster.arrive.aligned;" ::: "memory");
        asm volatile("barrier.cluster.wait.aligned;"   ::: "memory");
    }

    // safety: no CTA exits while peer may still read its SMEM
    asm volatile("barrier.cluster.arrive.aligned;" ::: "memory");
    asm volatile("barrier.cluster.wait.aligned;"   ::: "memory");
}

// =====================================================================
// Phase 3: out[b][v] = g_h[b] @ Wy + By.  2 batches per CTA.
// =====================================================================
__global__ __launch_bounds__(256)
void out_proj(const float* __restrict__ Wy, const float* __restrict__ By,
              float* __restrict__ out, int out_size) {
    if (blockIdx.x == 384) {
        if (out_size >= BB * VV + BB * HH) {
            for (int i = threadIdx.x; i < BB * HH; i += 256)
                out[BB * VV + i] = g_h[i];
        }
        return;
    }
    __shared__ float hs[2][HH];
    const int b0 = (blockIdx.x / 12) * 2;
    const int vt = blockIdx.x % 12;
    const int v  = vt * 256 + threadIdx.x;

    hs[0][threadIdx.x] = g_h[b0 * HH + threadIdx.x];
    hs[1][threadIdx.x] = g_h[(b0 + 1) * HH + threadIdx.x];
    __syncthreads();

    float acc0 = 0.f, acc1 = 0.f;
#pragma unroll 8
    for (int h = 0; h < HH; h++) {
        float w = Wy[(size_t)h * VV + v];
        acc0 += hs[0][h] * w;
        acc1 += hs[1][h] * w;
    }
    float by = By[v];
    out[(size_t)b0 * VV + v]       = acc0 + by;
    out[(size_t)(b0 + 1) * VV + v] = acc1 + by;
}

// =====================================================================
extern "C" void kernel_launch(void* const* d_in, const int* in_sizes, int n_in,
                              void* d_out, int out_size) {
    const int*   idx = (const int*)d_in[0];
    const float* emb = (const float*)d_in[1];
    const float* Wxh = (const float*)d_in[2];
    const float* Whh = (const float*)d_in[3];
    const float* Wy  = (const float*)d_in[4];
    const float* By  = (const float*)d_in[5];
    const float* Bh  = (const float*)d_in[6];
    float* out = (float*)d_out;

    static bool attr_set = false;
    if (!attr_set) {
        cudaFuncSetAttribute(gemm_emb,
                             cudaFuncAttributeMaxDynamicSharedMemorySize,
                             GEMM_SMEM_BYTES);
        attr_set = true;
    }

    gemm_emb<<<dim3(2, 256), 256, GEMM_SMEM_BYTES>>>(idx, emb, Wxh);
    rnn_scan<<<128, 512>>>(Whh, Bh);
    out_proj<<<385, 256>>>(Wy, By, out, out_size);
}

// round 12
// speedup vs baseline: 2.6085x; 1.3963x over previous
#include <cuda_runtime.h>
#include <cuda_bf16.h>
#include <cstdint>

#define BB 64
#define TT 512
#define EE 768
#define HH 256
#define VV 3072

__device__ float g_x[TT * BB * HH];   // xWxh laid out [t][b][h]
__device__ float g_h[BB * HH];        // final hidden

// bf16 hi/lo splits (prep kernel fills these)
__device__ __nv_bfloat16 g_embh[VV * EE];
__device__ __nv_bfloat16 g_embl[VV * EE];
__device__ __nv_bfloat16 g_wxh_h[HH * EE];   // TRANSPOSED: [n][k]
__device__ __nv_bfloat16 g_wxh_l[HH * EE];

// ---------- f32x2 helpers (scan) ----------
__device__ __forceinline__ unsigned long long pack2(float lo, float hi) {
    unsigned long long r;
    asm("mov.b64 %0, {%1, %2};" : "=l"(r) : "f"(lo), "f"(hi));
    return r;
}
__device__ __forceinline__ void unpack2(unsigned long long v, float& lo, float& hi) {
    asm("mov.b64 {%0, %1}, %2;" : "=f"(lo), "=f"(hi) : "l"(v));
}
__device__ __forceinline__ unsigned long long fma2(unsigned long long a,
                                                   unsigned long long b,
                                                   unsigned long long c) {
    unsigned long long d;
    asm("fma.rn.f32x2 %0, %1, %2, %3;" : "=l"(d) : "l"(a), "l"(b), "l"(c));
    return d;
}
__device__ __forceinline__ void cp16(uint32_t dst, const void* src) {
    asm volatile("cp.async.cg.shared.global [%0], [%1], 16;" :: "r"(dst), "l"(src));
}

// =====================================================================
// Prep: split emb and Wxh^T into bf16 hi/lo.
// =====================================================================
__global__ void prep_emb(const float* __restrict__ emb) {
    int i = blockIdx.x * blockDim.x + threadIdx.x;
    const int n = VV * EE;
    for (; i < n; i += gridDim.x * blockDim.x) {
        float v = emb[i];
        __nv_bfloat16 h = __float2bfloat16_rn(v);
        g_embh[i] = h;
        g_embl[i] = __float2bfloat16_rn(v - __bfloat162float(h));
    }
}
__global__ void prep_wxh(const float* __restrict__ Wxh) {
    int i = blockIdx.x * blockDim.x + threadIdx.x;
    const int n = HH * EE;
    for (; i < n; i += gridDim.x * blockDim.x) {
        int nn = i / EE, kk = i - nn * EE;
        float v = Wxh[kk * HH + nn];
        __nv_bfloat16 h = __float2bfloat16_rn(v);
        g_wxh_h[i] = h;
        g_wxh_l[i] = __float2bfloat16_rn(v - __bfloat162float(h));
    }
}

// =====================================================================
// Phase 1: g_x = gather(emb) @ Wxh  via mma.sync bf16, 3-product split.
// CTA tile M=128 x N=128, k-tile 32, 256 threads = 8 warps (4m x 2n),
// warp tile 32x64. Rows padded to 40 bf16 (80B) -> conflict-free frags.
// Smem per stage: A_h A_l B_h B_l, 10240B each = 40960B; 2 stages.
// =====================================================================
#define SA   40
#define TSZ  (128 * SA * 2)     // 10240
#define STG  (4 * TSZ)          // 40960
#define GSM  (2 * STG)          // 81920

__device__ __forceinline__ uint32_t lds32(uint32_t a) {
    uint32_t x;
    asm volatile("ld.shared.b32 %0, [%1];" : "=r"(x) : "r"(a));
    return x;
}
__device__ __forceinline__ void mma_bf16(float* d, const uint32_t* a,
                                         uint32_t b0, uint32_t b1) {
    asm volatile(
        "mma.sync.aligned.m16n8k16.row.col.f32.bf16.bf16.f32 "
        "{%0,%1,%2,%3}, {%4,%5,%6,%7}, {%8,%9}, {%0,%1,%2,%3};"
        : "+f"(d[0]), "+f"(d[1]), "+f"(d[2]), "+f"(d[3])
        : "r"(a[0]), "r"(a[1]), "r"(a[2]), "r"(a[3]), "r"(b0), "r"(b1));
}

__global__ __launch_bounds__(256, 2)
void gemm_mma(const int* __restrict__ idx) {
    extern __shared__ __align__(16) char smraw[];
    __shared__ int idx_s[128];

    const int tid = threadIdx.x;
    const int bm = blockIdx.y;   // 0..255
    const int bn = blockIdx.x;   // 0..1

    if (tid < 128) idx_s[tid] = idx[bm * 128 + tid];
    __syncthreads();

    const uint32_t sb = (uint32_t)__cvta_generic_to_shared(smraw);

    // ---- load mapping: 2 row-tasks per thread ----
    const int lr = tid & 127;
    const int lt = tid >> 7;   // 0: A tiles, 1: B tiles
    const __nv_bfloat16 *srcH, *srcL;
    if (lt == 0) {
        long r = idx_s[lr];
        srcH = g_embh + r * EE;
        srcL = g_embl + r * EE;
    } else {
        size_t n = (size_t)(bn * 128 + lr);
        srcH = g_wxh_h + n * EE;
        srcL = g_wxh_l + n * EE;
    }
    const uint32_t dstH = sb + lt * 20480 + lr * 80;
    const uint32_t dstL = dstH + 10240;

#define ISSUE(n, s)                                                          \
    do {                                                                     \
        const __nv_bfloat16* sh = srcH + (n) * 32;                           \
        const __nv_bfloat16* sl = srcL + (n) * 32;                           \
        const uint32_t so = (s) * (uint32_t)STG;                             \
        cp16(dstH + so,      sh);      cp16(dstH + so + 16, sh + 8);         \
        cp16(dstH + so + 32, sh + 16); cp16(dstH + so + 48, sh + 24);        \
        cp16(dstL + so,      sl);      cp16(dstL + so + 16, sl + 8);         \
        cp16(dstL + so + 32, sl + 16); cp16(dstL + so + 48, sl + 24);        \
        asm volatile("cp.async.commit_group;");                              \
    } while (0)

    // ---- mma mapping ----
    const int lane = tid & 31;
    const int w  = tid >> 5;
    const int wm = w & 3;     // 0..3, m offset wm*32
    const int wn = w >> 2;    // 0..1, n offset wn*64
    const int g  = lane >> 2;
    const int q  = lane & 3;

    float acc[2][8][4];
#pragma unroll
    for (int mi = 0; mi < 2; mi++)
#pragma unroll
        for (int nb = 0; nb < 8; nb++)
#pragma unroll
            for (int e = 0; e < 4; e++) acc[mi][nb][e] = 0.f;

    const int NT = EE / 32;   // 24

    ISSUE(0, 0);

    for (int i = 0; i < NT; i++) {
        const int s = i & 1;
        asm volatile("cp.async.wait_group 0;");
        __syncthreads();
        if (i + 1 < NT) ISSUE(i + 1, s ^ 1);

        const uint32_t aB = sb + s * (uint32_t)STG;            // A_h
        const uint32_t bB = aB + 20480;                        // B_h

#pragma unroll
        for (int ks = 0; ks < 2; ks++) {
            const int kq = ks * 16 + 2 * q;     // bf16 col of a0/b0

            uint32_t ah[2][4], al[2][4];
#pragma unroll
            for (int mi = 0; mi < 2; mi++) {
                const int r = wm * 32 + mi * 16 + g;
                const uint32_t o00 = aB + (uint32_t)((r * SA + kq) * 2);
                const uint32_t o10 = aB + (uint32_t)(((r + 8) * SA + kq) * 2);
                ah[mi][0] = lds32(o00);
                ah[mi][1] = lds32(o10);
                ah[mi][2] = lds32(o00 + 16);
                ah[mi][3] = lds32(o10 + 16);
                al[mi][0] = lds32(o00 + 10240);
                al[mi][1] = lds32(o10 + 10240);
                al[mi][2] = lds32(o00 + 16 + 10240);
                al[mi][3] = lds32(o10 + 16 + 10240);
            }

#pragma unroll
            for (int nb = 0; nb < 8; nb++) {
                const int n = wn * 64 + nb * 8 + g;
                const uint32_t ob = bB + (uint32_t)((n * SA + kq) * 2);
                uint32_t bh0 = lds32(ob);
                uint32_t bh1 = lds32(ob + 16);
                uint32_t bl0 = lds32(ob + 10240);
                uint32_t bl1 = lds32(ob + 16 + 10240);
#pragma unroll
                for (int mi = 0; mi < 2; mi++) {
                    mma_bf16(acc[mi][nb], ah[mi], bh0, bh1);   // hi*hi
                    mma_bf16(acc[mi][nb], ah[mi], bl0, bl1);   // hi*lo
                    mma_bf16(acc[mi][nb], al[mi], bh0, bh1);   // lo*hi
                }
            }
        }
        __syncthreads();
    }
#undef ISSUE

    // ---- epilogue: acc -> g_x (row m -> (b,t)) ----
#pragma unroll
    for (int mi = 0; mi < 2; mi++) {
#pragma unroll
        for (int nb = 0; nb < 8; nb++) {
            const int m0 = bm * 128 + wm * 32 + mi * 16 + g;
            const int cc = bn * 128 + wn * 64 + nb * 8 + 2 * q;
            {
                const int b = m0 >> 9, t = m0 & 511;
                float2 v = make_float2(acc[mi][nb][0], acc[mi][nb][1]);
                *reinterpret_cast<float2*>(
                    g_x + (size_t)t * (BB * HH) + b * HH + cc) = v;
            }
            {
                const int m1 = m0 + 8;
                const int b = m1 >> 9, t = m1 & 511;
                float2 v = make_float2(acc[mi][nb][2], acc[mi][nb][3]);
                *reinterpret_cast<float2*>(
                    g_x + (size_t)t * (BB * HH) + b * HH + cc) = v;
            }
        }
    }
}

// =====================================================================
// Phase 2: recurrent scan (PROVEN structure, 1024 thr, one cluster
// barrier + psum/__syncthreads per step, static w2 indexing).
// =====================================================================
__global__ __launch_bounds__(1024, 1) __cluster_dims__(2, 1, 1)
void rnn_scan(const float* __restrict__ Whh, const float* __restrict__ Bh) {
    __shared__ __align__(16) float hbuf[2][256];
    __shared__ float psum[7][128];

    const int tid = threadIdx.x;
    const int b = blockIdx.x >> 1;
    uint32_t rank;
    asm("mov.u32 %0, %%cluster_ctarank;" : "=r"(rank));
    const uint32_t prank = rank ^ 1u;

    const int jl = tid & 127;
    const int c  = tid >> 7;            // 0..7
    const int j  = (int)rank * 128 + jl;
    const int i0 = c * 32;

    unsigned long long w2[16];
#pragma unroll
    for (int p = 0; p < 16; p++) {
        int i = i0 + 2 * p;
        w2[p] = pack2(Whh[i * HH + j], Whh[(i + 1) * HH + j]);
    }
    float bh = 0.f;
    if (c == 0) bh = Bh[j];

    const uint32_t hb_base = (uint32_t)__cvta_generic_to_shared(&hbuf[0][0]);

    uint32_t peer_h[2];
#pragma unroll
    for (int bb = 0; bb < 2; bb++) {
        uint32_t lh = hb_base + bb * 1024 + j * 4;
        asm("mapa.shared::cluster.u32 %0, %1, %2;"
            : "=r"(peer_h[bb]) : "r"(lh), "r"(prank));
    }

    if (tid < 256) hbuf[0][tid] = 0.f;
    __syncthreads();
    asm volatile("barrier.cluster.arrive.aligned;" ::: "memory");
    asm volatile("barrier.cluster.wait.aligned;"   ::: "memory");

    const float* xptr = g_x + b * HH + j;
    float xv_cur = 0.f;
    if (c == 0) xv_cur = xptr[0];

    for (int t = 0; t < TT; t++) {
        const int cur = t & 1;
        const int nb  = cur ^ 1;

        float xv = 0.f;
        if (c == 0) {
            xv = xv_cur;
            if (t + 1 < TT) xv_cur = xptr[(size_t)(t + 1) * (BB * HH)];
        }

        const uint32_t ha = hb_base + cur * 1024 + i0 * 4;
        unsigned long long acc0 = 0ull, acc1 = 0ull;
#pragma unroll
        for (int p = 0; p < 4; p++) {
            unsigned long long h0, h1, h2, h3;
            asm volatile("ld.shared.v2.u64 {%0,%1}, [%2];"
                         : "=l"(h0), "=l"(h1) : "r"(ha + p * 32));
            asm volatile("ld.shared.v2.u64 {%0,%1}, [%2];"
                         : "=l"(h2), "=l"(h3) : "r"(ha + p * 32 + 16));
            acc0 = fma2(w2[4 * p + 0], h0, acc0);
            acc1 = fma2(w2[4 * p + 1], h1, acc1);
            acc0 = fma2(w2[4 * p + 2], h2, acc0);
            acc1 = fma2(w2[4 * p + 3], h3, acc1);
        }
        float l0, u0, l1, u1;
        unpack2(acc0, l0, u0); unpack2(acc1, l1, u1);
        float part = (l0 + u0) + (l1 + u1);

        if (c > 0) psum[c - 1][jl] = part;
        __syncthreads();

        if (c == 0) {
            float s = part + psum[0][jl] + psum[1][jl] + psum[2][jl]
                           + psum[3][jl] + psum[4][jl] + psum[5][jl]
                           + psum[6][jl] + xv + bh;
            float hn = tanhf(s);
            hbuf[nb][j] = hn;                               // local copy
            asm volatile("st.shared::cluster.f32 [%0], %1;" // peer copy
                         :: "r"(peer_h[nb]), "f"(hn) : "memory");
            if (t == TT - 1) g_h[b * HH + j] = hn;
        }

        asm volatile("barrier.cluster.arrive.aligned;" ::: "memory");
        asm volatile("barrier.cluster.wait.aligned;"   ::: "memory");
    }
}

// =====================================================================
// Phase 3: out[b][v] = g_h[b] @ Wy + By.  2 batches per CTA.
// =====================================================================
__global__ __launch_bounds__(256)
void out_proj(const float* __restrict__ Wy, const float* __restrict__ By,
              float* __restrict__ out, int out_size) {
    if (blockIdx.x == 384) {
        if (out_size >= BB * VV + BB * HH) {
            for (int i = threadIdx.x; i < BB * HH; i += 256)
                out[BB * VV + i] = g_h[i];
        }
        return;
    }
    __shared__ float hs[2][HH];
    const int b0 = (blockIdx.x / 12) * 2;
    const int vt = blockIdx.x % 12;
    const int v  = vt * 256 + threadIdx.x;

    hs[0][threadIdx.x] = g_h[b0 * HH + threadIdx.x];
    hs[1][threadIdx.x] = g_h[(b0 + 1) * HH + threadIdx.x];
    __syncthreads();

    float acc0 = 0.f, acc1 = 0.f;
#pragma unroll 8
    for (int h = 0; h < HH; h++) {
        float w = Wy[(size_t)h * VV + v];
        acc0 += hs[0][h] * w;
        acc1 += hs[1][h] * w;
    }
    float by = By[v];
    out[(size_t)b0 * VV + v]       = acc0 + by;
    out[(size_t)(b0 + 1) * VV + v] = acc1 + by;
}

// =====================================================================
extern "C" void kernel_launch(void* const* d_in, const int* in_sizes, int n_in,
                              void* d_out, int out_size) {
    const int*   idx = (const int*)d_in[0];
    const float* emb = (const float*)d_in[1];
    const float* Wxh = (const float*)d_in[2];
    const float* Whh = (const float*)d_in[3];
    const float* Wy  = (const float*)d_in[4];
    const float* By  = (const float*)d_in[5];
    const float* Bh  = (const float*)d_in[6];
    float* out = (float*)d_out;

    static bool attr_set = false;
    if (!attr_set) {
        cudaFuncSetAttribute(gemm_mma,
                             cudaFuncAttributeMaxDynamicSharedMemorySize,
                             GSM);
        attr_set = true;
    }

    prep_emb<<<2048, 256>>>(emb);
    prep_wxh<<<192, 256>>>(Wxh);
    gemm_mma<<<dim3(2, 256), 256, GSM>>>(idx);
    rnn_scan<<<128, 1024>>>(Whh, Bh);
    out_proj<<<385, 256>>>(Wy, By, out, out_size);
}